// round 2
// baseline (speedup 1.0000x reference)
#include <cuda_runtime.h>
#include <cstdint>

// ---------------------------------------------------------------------------
// PredNetNoMap (LaneGCN decoder head), N=100000 actors, K=6 modes, P=30, D=128
// Pipeline (10 graph-capturable kernel launches, no allocs, no syncs):
//   1. pred1 : buf1[k,n]  = relu(gn(actors @ W1[k]))            (GEMM+GN fused)
//   2. pred2 : buf2[k,n]  = relu(gn(buf1 @ W2[k]) + actors)     (GEMM+GN+res)
//   3. predo : reg[n,k]   = buf2 @ Wo[k] + bo[k] + ctr[n]       (GEMM, 60 cols)
//   4. dist0 : buf1[n*K+k]= relu(dist @ W0 + b0)                (tiny map)
//   5. dist1 : buf2       = relu(gn(buf1 @ dist_W1))            (GEMM+GN)
//   6. a2    : a2[n]      = actors @ agt_W[128:256]             (GEMM plain)
//   7. agt   : feats      = relu(gn(buf2 @ agt_W[0:128] + a2))  (GEMM+pre+GN)
//   8. cls1  : buf1       = relu(gn(feats @ cls_W1))            (GEMM+GN)
//   9. cls2  : clsraw     = relu(gn(buf1@cls_W2)+feats) . Wo+bo (GEMM+GN+dot)
//  10. final : softmax(K=6), stable desc sort, gather reg, write outputs
// Output layout: [cls_sorted (600000)] [reg_sorted (36000000)] [feats (76800000)]
// ---------------------------------------------------------------------------

namespace {
constexpr int  NACT  = 100000;
constexpr int  KM    = 6;
constexpr int  DD    = 128;
constexpr int  OUT2P = 60;                       // 2*P
constexpr long TOT_NK = (long)NACT * KM;         // 600000
constexpr long OFF_REG   = TOT_NK;               // cls_sorted first
constexpr long OFF_FEATS = OFF_REG + TOT_NK * OUT2P;   // 36,600,000
constexpr int  BM = 128;
constexpr int  BK = 8;
}

// Scratch (static device memory: allowed; no runtime allocation)
__device__ float g_buf1[TOT_NK * DD];            // 307 MB
__device__ float g_buf2[TOT_NK * DD];            // 307 MB
__device__ float g_a2[(long)NACT * DD];          // 51 MB
__device__ float g_reg[TOT_NK * OUT2P];          // 144 MB (unsorted reg)
__device__ float g_cls[TOT_NK];                  // 2.4 MB (raw logits)

struct GemmParams {
    const float* A;      long aStrideK;          // per-z A offset (elements)
    const float* B;      long bStrideK; int ldB; // weight per-z stride / leading dim
    int M; int Ncols;                            // rows per z-slice, valid cols
    float* Out; int ldOut;
    const float* gamma;  const float* beta;      // groupnorm affine (+ z*DD)
    const float* resid;                          // post-GN residual, row-indexed
    const float* preadd; int preDiv;             // pre-GN add, row n -> preadd[n/preDiv]
    const float* biasN;                          // per-col bias (predo), + z*Ncols
    const float* ctrs;                           // actor ctrs (predo)
    const float* wo; const float* wob;           // cls head weight/bias
    float* clsOut;                               // cls logits out
};

// EPI: 0 plain store | 1 GN+relu | 2 GN+resid+relu | 3 preadd+GN+relu
//      4 bias+ctr, store to [n*KM+z] (predo) | 5 GN+resid+relu+dot(wo)->clsOut
template<int BN, int TN, int EPI>
__global__ __launch_bounds__(256)
void gemm_k(GemmParams p) {
    const int z = blockIdx.z;
    const int rowBase = blockIdx.y * BM;
    const int tid = threadIdx.x;
    const int tn = tid & 15;       // 16 col-groups
    const int tm = tid >> 4;       // 16 row-groups (8 rows each)

    const float* A = p.A + (long)z * p.aStrideK;
    const float* B = p.B + (long)z * p.bStrideK;

    __shared__ float As[BK][BM];
    __shared__ float Bs[BK][BN];
    __shared__ float red[BM][17];
    __shared__ float red2[BM][17];
    __shared__ float rowMean[BM];
    __shared__ float rowRstd[BM];

    float acc[8][TN];
#pragma unroll
    for (int i = 0; i < 8; i++)
#pragma unroll
        for (int j = 0; j < TN; j++) acc[i][j] = 0.f;

    // A-tile load mapping: 256 threads -> 128 rows x 2 float4
    const int ar  = tid >> 1;
    const int ac4 = (tid & 1) * 4;
    const int aRow = rowBase + ar;
    const bool aValid = aRow < p.M;
    const float* aPtr = A + (long)aRow * DD + ac4;

    for (int kk = 0; kk < DD; kk += BK) {
        float4 av = make_float4(0.f, 0.f, 0.f, 0.f);
        if (aValid) av = *reinterpret_cast<const float4*>(aPtr + kk);
        As[ac4 + 0][ar] = av.x;
        As[ac4 + 1][ar] = av.y;
        As[ac4 + 2][ar] = av.z;
        As[ac4 + 3][ar] = av.w;
#pragma unroll
        for (int t = 0; t < (BK * BN) / 256; t++) {
            int e = tid + t * 256;
            int br = e / BN, bc = e % BN;
            float v = 0.f;
            if (bc < p.Ncols) v = B[(long)(kk + br) * p.ldB + bc];
            Bs[br][bc] = v;
        }
        __syncthreads();
#pragma unroll
        for (int k8 = 0; k8 < BK; k8++) {
            float af[8], bf[TN];
#pragma unroll
            for (int i = 0; i < 8; i++) af[i] = As[k8][tm * 8 + i];
#pragma unroll
            for (int j = 0; j < TN; j++) bf[j] = Bs[k8][tn * TN + j];
#pragma unroll
            for (int i = 0; i < 8; i++)
#pragma unroll
                for (int j = 0; j < TN; j++) acc[i][j] = fmaf(af[i], bf[j], acc[i][j]);
        }
        __syncthreads();
    }

    if (EPI == 0) {
#pragma unroll
        for (int i = 0; i < 8; i++) {
            int n = rowBase + tm * 8 + i;
            if (n < p.M) {
#pragma unroll
                for (int j = 0; j < TN; j++)
                    p.Out[((long)z * p.M + n) * p.ldOut + tn * TN + j] = acc[i][j];
            }
        }
        return;
    }
    if (EPI == 4) {
#pragma unroll
        for (int i = 0; i < 8; i++) {
            int n = rowBase + tm * 8 + i;
            if (n < p.M) {
#pragma unroll
                for (int j = 0; j < TN; j++) {
                    int c = tn * TN + j;
                    if (c < p.Ncols) {
                        float v = acc[i][j] + p.biasN[z * p.Ncols + c]
                                + p.ctrs[(long)n * 2 + (c & 1)];
                        p.Out[((long)n * KM + z) * p.ldOut + c] = v;
                    }
                }
            }
        }
        return;
    }

    // ---- GroupNorm path ----
    if (EPI == 3) {
#pragma unroll
        for (int i = 0; i < 8; i++) {
            int n = rowBase + tm * 8 + i;
            if (n < p.M) {
                const float* pa = p.preadd + (long)(n / p.preDiv) * DD;
#pragma unroll
                for (int j = 0; j < TN; j++) acc[i][j] += pa[tn * TN + j];
            }
        }
    }
#pragma unroll
    for (int i = 0; i < 8; i++) {
        float s = 0.f, q = 0.f;
#pragma unroll
        for (int j = 0; j < TN; j++) { s += acc[i][j]; q += acc[i][j] * acc[i][j]; }
        red [tm * 8 + i][tn] = s;
        red2[tm * 8 + i][tn] = q;
    }
    __syncthreads();
    if (tid < BM) {
        float s = 0.f, q = 0.f;
#pragma unroll
        for (int t = 0; t < 16; t++) { s += red[tid][t]; q += red2[tid][t]; }
        float m   = s * (1.f / DD);
        float var = q * (1.f / DD) - m * m;
        rowMean[tid] = m;
        rowRstd[tid] = rsqrtf(var + 1e-5f);
    }
    __syncthreads();

    const float* gam = p.gamma + (long)z * DD;
    const float* bet = p.beta  + (long)z * DD;
#pragma unroll
    for (int i = 0; i < 8; i++) {
        int mr = tm * 8 + i;
        int n  = rowBase + mr;
        float m = rowMean[mr], rs = rowRstd[mr];
#pragma unroll
        for (int j = 0; j < TN; j++) {
            int c = tn * TN + j;
            float v = (acc[i][j] - m) * rs * gam[c] + bet[c];
            if ((EPI == 2 || EPI == 5) && n < p.M) v += p.resid[(long)n * DD + c];
            acc[i][j] = fmaxf(v, 0.f);
        }
    }
    if (EPI == 5) {
#pragma unroll
        for (int i = 0; i < 8; i++) {
            float s = 0.f;
#pragma unroll
            for (int j = 0; j < TN; j++) s += acc[i][j] * p.wo[tn * TN + j];
            red[tm * 8 + i][tn] = s;
        }
        __syncthreads();
        if (tid < BM) {
            float s = 0.f;
#pragma unroll
            for (int t = 0; t < 16; t++) s += red[tid][t];
            int n = rowBase + tid;
            if (n < p.M) p.clsOut[n] = s + p.wob[0];
        }
        return;
    }
#pragma unroll
    for (int i = 0; i < 8; i++) {
        int n = rowBase + tm * 8 + i;
        if (n < p.M) {
#pragma unroll
            for (int j = 0; j < TN; j++)
                p.Out[((long)z * p.M + n) * p.ldOut + tn * TN + j] = acc[i][j];
        }
    }
}

// dh0[n*K+k, c] = relu((ctr - dest_ctr) . W0[:,c] + b0[c]); dest from reg p=29
__global__ void dist0_k(const float* __restrict__ ctrs, const float* __restrict__ reg,
                        const float* __restrict__ W0, const float* __restrict__ b0,
                        float* __restrict__ out) {
    long idx = (long)blockIdx.x * blockDim.x + threadIdx.x;
    if (idx >= TOT_NK * DD) return;
    int  c = (int)(idx & (DD - 1));
    long r = idx >> 7;               // n*K + k
    long n = r / KM;
    float dx = ctrs[n * 2 + 0] - reg[r * OUT2P + 58];
    float dy = ctrs[n * 2 + 1] - reg[r * OUT2P + 59];
    float v = fmaf(dx, W0[c], fmaf(dy, W0[DD + c], b0[c]));
    out[idx] = fmaxf(v, 0.f);
}

// softmax over K=6, stable descending sort, reorder cls + reg into d_out
__global__ void final_k(const float* __restrict__ clsRaw, const float* __restrict__ reg,
                        float* __restrict__ out) {
    long gw = ((long)blockIdx.x * blockDim.x + threadIdx.x) >> 5;  // one warp per actor
    int lane = threadIdx.x & 31;
    if (gw >= NACT) return;
    long n = gw;
    float v[KM];
#pragma unroll
    for (int k = 0; k < KM; k++) v[k] = clsRaw[n * KM + k];
    float mx = v[0];
#pragma unroll
    for (int k = 1; k < KM; k++) mx = fmaxf(mx, v[k]);
    float e[KM]; float s = 0.f;
#pragma unroll
    for (int k = 0; k < KM; k++) { e[k] = expf(v[k] - mx); s += e[k]; }
    float inv = 1.f / s;
    int order[KM]; bool used[KM];
#pragma unroll
    for (int k = 0; k < KM; k++) used[k] = false;
#pragma unroll
    for (int j = 0; j < KM; j++) {        // stable selection: strict >, first index wins
        int best = 0; float bv = -1e30f;
#pragma unroll
        for (int k = 0; k < KM; k++)
            if (!used[k] && v[k] > bv) { bv = v[k]; best = k; }
        used[best] = true;
        order[j] = best;
    }
    if (lane < KM) out[n * KM + lane] = e[order[lane]] * inv;
    const float* src0 = reg + n * KM * OUT2P;
    float* dst0 = out + OFF_REG + n * KM * OUT2P;
#pragma unroll
    for (int j = 0; j < KM; j++) {
        const float* src = src0 + order[j] * OUT2P;
        float* dst = dst0 + (long)j * OUT2P;
        for (int t = lane; t < OUT2P; t += 32) dst[t] = src[t];
    }
}

extern "C" void kernel_launch(void* const* d_in, const int* in_sizes, int n_in,
                              void* d_out, int out_size) {
    const float* actors  = (const float*)d_in[0];
    const float* ctrs    = (const float*)d_in[1];
    const float* pred_W1 = (const float*)d_in[2];
    const float* pred_g1 = (const float*)d_in[3];
    const float* pred_b1 = (const float*)d_in[4];
    const float* pred_W2 = (const float*)d_in[5];
    const float* pred_g2 = (const float*)d_in[6];
    const float* pred_b2 = (const float*)d_in[7];
    const float* pred_Wo = (const float*)d_in[8];
    const float* pred_bo = (const float*)d_in[9];
    const float* dist_W0 = (const float*)d_in[10];
    const float* dist_b0 = (const float*)d_in[11];
    const float* dist_W1 = (const float*)d_in[12];
    const float* dist_g1 = (const float*)d_in[13];
    const float* dist_b1 = (const float*)d_in[14];
    const float* agt_W   = (const float*)d_in[15];
    const float* agt_g   = (const float*)d_in[16];
    const float* agt_b   = (const float*)d_in[17];
    const float* cls_W1  = (const float*)d_in[18];
    const float* cls_g1  = (const float*)d_in[19];
    const float* cls_b1  = (const float*)d_in[20];
    const float* cls_W2  = (const float*)d_in[21];
    const float* cls_g2  = (const float*)d_in[22];
    const float* cls_b2  = (const float*)d_in[23];
    const float* cls_Wo  = (const float*)d_in[24];
    const float* cls_bo  = (const float*)d_in[25];
    float* out = (float*)d_out;

    float *buf1, *buf2, *a2, *reg, *clsraw;
    cudaGetSymbolAddress((void**)&buf1,   g_buf1);
    cudaGetSymbolAddress((void**)&buf2,   g_buf2);
    cudaGetSymbolAddress((void**)&a2,     g_a2);
    cudaGetSymbolAddress((void**)&reg,    g_reg);
    cudaGetSymbolAddress((void**)&clsraw, g_cls);

    float* feats = out + OFF_FEATS;

    const int gy_N  = (NACT + BM - 1) / BM;            // 782
    const int gy_NK = ((int)TOT_NK + BM - 1) / BM;     // 4688

    GemmParams p;

    // 1. pred1: buf1[k*N+n] = relu(gn(actors @ W1[k], g1[k], b1[k]))
    p = {}; p.A = actors; p.aStrideK = 0; p.B = pred_W1; p.bStrideK = (long)DD*DD; p.ldB = DD;
    p.M = NACT; p.Ncols = DD; p.Out = buf1; p.ldOut = DD; p.gamma = pred_g1; p.beta = pred_b1;
    gemm_k<128,8,1><<<dim3(1, gy_N, KM), 256>>>(p);

    // 2. pred2: buf2 = relu(gn(buf1 @ W2[k]) + actors)
    p = {}; p.A = buf1; p.aStrideK = (long)NACT*DD; p.B = pred_W2; p.bStrideK = (long)DD*DD; p.ldB = DD;
    p.M = NACT; p.Ncols = DD; p.Out = buf2; p.ldOut = DD; p.gamma = pred_g2; p.beta = pred_b2;
    p.resid = actors;
    gemm_k<128,8,2><<<dim3(1, gy_N, KM), 256>>>(p);

    // 3. predo: reg[(n*K+k)*60+c] = buf2 @ Wo[k] + bo[k] + ctr[n][c&1]
    p = {}; p.A = buf2; p.aStrideK = (long)NACT*DD; p.B = pred_Wo; p.bStrideK = (long)DD*OUT2P; p.ldB = OUT2P;
    p.M = NACT; p.Ncols = OUT2P; p.Out = reg; p.ldOut = OUT2P; p.biasN = pred_bo; p.ctrs = ctrs;
    gemm_k<64,4,4><<<dim3(1, gy_N, KM), 256>>>(p);

    // 4. dist0 -> buf1 (layout [n*K+k, 128])
    {
        long total = TOT_NK * DD;
        dist0_k<<<(int)((total + 255) / 256), 256>>>(ctrs, reg, dist_W0, dist_b0, buf1);
    }

    // 5. dist1: buf2 = relu(gn(buf1 @ dist_W1))
    p = {}; p.A = buf1; p.aStrideK = 0; p.B = dist_W1; p.bStrideK = 0; p.ldB = DD;
    p.M = (int)TOT_NK; p.Ncols = DD; p.Out = buf2; p.ldOut = DD; p.gamma = dist_g1; p.beta = dist_b1;
    gemm_k<128,8,1><<<dim3(1, gy_NK, 1), 256>>>(p);

    // 6. a2 = actors @ agt_W[128:256]   (shared across K modes)
    p = {}; p.A = actors; p.aStrideK = 0; p.B = agt_W + DD*DD; p.bStrideK = 0; p.ldB = DD;
    p.M = NACT; p.Ncols = DD; p.Out = a2; p.ldOut = DD;
    gemm_k<128,8,0><<<dim3(1, gy_N, 1), 256>>>(p);

    // 7. agt: feats = relu(gn(buf2 @ agt_W[0:128] + a2[n]))
    p = {}; p.A = buf2; p.aStrideK = 0; p.B = agt_W; p.bStrideK = 0; p.ldB = DD;
    p.M = (int)TOT_NK; p.Ncols = DD; p.Out = feats; p.ldOut = DD; p.gamma = agt_g; p.beta = agt_b;
    p.preadd = a2; p.preDiv = KM;
    gemm_k<128,8,3><<<dim3(1, gy_NK, 1), 256>>>(p);

    // 8. cls1: buf1 = relu(gn(feats @ cls_W1))
    p = {}; p.A = feats; p.aStrideK = 0; p.B = cls_W1; p.bStrideK = 0; p.ldB = DD;
    p.M = (int)TOT_NK; p.Ncols = DD; p.Out = buf1; p.ldOut = DD; p.gamma = cls_g1; p.beta = cls_b1;
    gemm_k<128,8,1><<<dim3(1, gy_NK, 1), 256>>>(p);

    // 9. cls2 fused with cls_Wo dot: clsraw = relu(gn(buf1@cls_W2)+feats) . Wo + bo
    p = {}; p.A = buf1; p.aStrideK = 0; p.B = cls_W2; p.bStrideK = 0; p.ldB = DD;
    p.M = (int)TOT_NK; p.Ncols = DD; p.ldOut = DD; p.gamma = cls_g2; p.beta = cls_b2;
    p.resid = feats; p.wo = cls_Wo; p.wob = cls_bo; p.clsOut = clsraw;
    gemm_k<128,8,5><<<dim3(1, gy_NK, 1), 256>>>(p);

    // 10. softmax + stable sort + gather
    {
        long threads = (long)NACT * 32;
        final_k<<<(int)((threads + 255) / 256), 256>>>(clsraw, reg, out);
    }
}

// round 5
// speedup vs baseline: 3.2045x; 3.2045x over previous
#include <cuda_runtime.h>
#include <cstdint>

// ---------------------------------------------------------------------------
// PredNetNoMap — TF32 mma.sync fused implementation.
// 6 launches:
//  1. pred12 : buf2 = relu(gn(relu(gn(actors@W1[k]))@W2[k]) + actors)   (2-layer fused)
//  2. predo  : reg  = buf2@Wo[k] + bo[k] + ctr                          (1-layer)
//  3. a2     : a2   = actors @ agt_W[128:256]                           (1-layer)
//  4. distagt: feats= relu(gn(relu(gn(AGEN@dist_W1))@agt_Wtop + a2))    (A generated in smem)
//  5. cls12  : cls  = (relu(gn(relu(gn(feats@cW1))@cW2)+feats)) . Wo+bo (2-layer + dot)
//  6. final  : softmax(K=6) + stable desc sort + gather
// ---------------------------------------------------------------------------

namespace {
constexpr int  NACT  = 100000;
constexpr int  KM    = 6;
constexpr int  DD    = 128;
constexpr int  OUT2P = 60;
constexpr long TOT_NK = (long)NACT * KM;                 // 600000
constexpr long OFF_REG   = TOT_NK;
constexpr long OFF_FEATS = OFF_REG + TOT_NK * OUT2P;     // 36,600,000

constexpr int LDA  = 132;   // pad ≡ 4 (mod 32): conflict-free a-frag LDS
constexpr int LDBS = 136;   // pad ≡ 8 (mod 32): conflict-free b-frag LDS
constexpr int SM_AS   = 0;
constexpr int SM_BS   = SM_AS  + 128 * LDA;
constexpr int SM_ASV  = SM_BS  + 128 * LDBS;
constexpr int SM_RED  = SM_ASV + 128 * LDA;
constexpr int SM_RED2 = SM_RED  + 128 * 9;
constexpr int SM_STAT = SM_RED2 + 128 * 9;
constexpr int SMEM_FLOATS = SM_STAT + 256;
constexpr int SMEM_BYTES  = SMEM_FLOATS * 4;             // 215,040 B
}

// scratch (static device memory; no runtime allocation)
__device__ float g_buf2[TOT_NK * DD];
__device__ float g_a2[(long)NACT * DD];
__device__ float g_reg[TOT_NK * OUT2P];
__device__ float g_cls[TOT_NK];

struct KParams {
    const float* A;  long aStride;
    const float* B1; long b1Stride; int ldB1; int ncols1;
    const float* B2; long b2Stride;
    int M;
    const float* g1; const float* bt1;     // mid GN affine (+z*DD)
    const float* g2; const float* bt2;     // out GN affine (+z*DD)
    float* Out;
    const float* pre;                      // EPIO3 pre-GN add (row nk/6)
    const float* biasN; const float* ctrs; // EPIO4 / AGEN
    const float* wo; const float* wob; float* clsOut;   // EPIO5
    const float* dW0; const float* db0; const float* dReg; // AGEN
};

// ---------------- low-level helpers ----------------
__device__ __forceinline__ void cp16(float* dstSm, const float* src, bool valid) {
    uint32_t d = (uint32_t)__cvta_generic_to_shared(dstSm);
    int sz = valid ? 16 : 0;
    asm volatile("cp.async.cg.shared.global [%0], [%1], 16, %2;\n"
                 :: "r"(d), "l"(src), "r"(sz));
}
__device__ __forceinline__ void cpcommit() { asm volatile("cp.async.commit_group;\n"); }
template<int N> __device__ __forceinline__ void cpwait() {
    asm volatile("cp.async.wait_group %0;\n" :: "n"(N));
}
__device__ __forceinline__ uint32_t f2tf(float f) {
    uint32_t u;
    asm("cvt.rna.tf32.f32 %0, %1;" : "=r"(u) : "f"(f));
    return u;
}
__device__ __forceinline__ void mma8(float& d0, float& d1, float& d2, float& d3,
                                     uint32_t a0, uint32_t a1, uint32_t a2, uint32_t a3,
                                     uint32_t b0, uint32_t b1) {
    asm volatile("mma.sync.aligned.m16n8k8.row.col.f32.tf32.tf32.f32 "
                 "{%0,%1,%2,%3},{%4,%5,%6,%7},{%8,%9},{%0,%1,%2,%3};"
                 : "+f"(d0), "+f"(d1), "+f"(d2), "+f"(d3)
                 : "r"(a0), "r"(a1), "r"(a2), "r"(a3), "r"(b0), "r"(b1));
}

__device__ __forceinline__ void loadA_chunk(float* As, const float* Agl,
                                            int rowBase, int M, int c, int tid) {
#pragma unroll
    for (int t = 0; t < 4; t++) {
        int task = t * 256 + tid;
        int row  = task >> 3;
        int col  = c * 32 + (task & 7) * 4;
        bool v = (rowBase + row) < M;
        cp16(As + row * LDA + col, Agl + (long)(rowBase + row) * DD + col, v);
    }
}
__device__ __forceinline__ void loadB_chunk(float* Bs, const float* Bgl,
                                            int ldB, int ncols, int c, int tid) {
#pragma unroll
    for (int t = 0; t < 4; t++) {
        int task = t * 256 + tid;
        int kr   = task >> 5;
        int col  = (task & 31) * 4;
        int k    = c * 32 + kr;
        bool v = col < ncols;
        cp16(Bs + k * LDBS + col, Bgl + (long)k * ldB + col, v);
    }
}

__device__ __forceinline__ void compute_chunk(float acc[2][8][4], const float* Asrc,
                                              const float* Bs, int base,
                                              int mw, int nw, int gid, int tig) {
#pragma unroll
    for (int k8 = 0; k8 < 4; k8++) {
        int kb = base + k8 * 8;
        uint32_t a[2][4];
#pragma unroll
        for (int mt = 0; mt < 2; mt++) {
            int r = mw * 32 + mt * 16 + gid;
            a[mt][0] = f2tf(Asrc[r * LDA + kb + tig]);
            a[mt][1] = f2tf(Asrc[(r + 8) * LDA + kb + tig]);
            a[mt][2] = f2tf(Asrc[r * LDA + kb + tig + 4]);
            a[mt][3] = f2tf(Asrc[(r + 8) * LDA + kb + tig + 4]);
        }
#pragma unroll
        for (int nt = 0; nt < 8; nt++) {
            int cn = nw * 64 + nt * 8 + gid;
            uint32_t b0 = f2tf(Bs[(kb + tig) * LDBS + cn]);
            uint32_t b1 = f2tf(Bs[(kb + tig + 4) * LDBS + cn]);
#pragma unroll
            for (int mt = 0; mt < 2; mt++)
                mma8(acc[mt][nt][0], acc[mt][nt][1], acc[mt][nt][2], acc[mt][nt][3],
                     a[mt][0], a[mt][1], a[mt][2], a[mt][3], b0, b1);
        }
    }
}

// GN row statistics from acc into rstat (mean[128], rstd[128])
__device__ __forceinline__ void gn_stats(float acc[2][8][4], float* red, float* red2,
                                         float* rstat, int mw, int gid, int tig,
                                         int grp, int tid) {
#pragma unroll
    for (int mt = 0; mt < 2; mt++) {
#pragma unroll
        for (int h = 0; h < 2; h++) {
            int r = mw * 32 + mt * 16 + gid + h * 8;
            float s = 0.f, q = 0.f;
#pragma unroll
            for (int nt = 0; nt < 8; nt++) {
                float v0 = acc[mt][nt][h * 2], v1 = acc[mt][nt][h * 2 + 1];
                s += v0 + v1;
                q += fmaf(v0, v0, v1 * v1);
            }
            red [r * 9 + grp] = s;
            red2[r * 9 + grp] = q;
        }
    }
    __syncthreads();
    if (tid < 128) {
        float s = 0.f, q = 0.f;
#pragma unroll
        for (int g = 0; g < 8; g++) { s += red[tid * 9 + g]; q += red2[tid * 9 + g]; }
        float m   = s * (1.f / DD);
        float var = q * (1.f / DD) - m * m;
        rstat[tid]       = m;
        rstat[128 + tid] = rsqrtf(var + 1e-5f);
    }
    __syncthreads();
}

// EPIO: 0 plain store | 2 GN+resid(As)+relu | 3 preadd+GN+relu
//       4 bias+ctr -> reg layout | 5 GN+resid(As)+relu+dot(wo)->clsOut
template<bool TWOLAYER, bool AGEN, int EPIO>
__global__ __launch_bounds__(256, 1)
void fused_k(KParams p) {
    extern __shared__ float sm[];
    float* As    = sm + SM_AS;
    float* Bs    = sm + SM_BS;
    float* Asv   = sm + SM_ASV;
    float* red   = sm + SM_RED;
    float* red2  = sm + SM_RED2;
    float* rstat = sm + SM_STAT;

    const int tid  = threadIdx.x;
    const int lane = tid & 31;
    const int w    = tid >> 5;
    const int gid  = lane >> 2, tig = lane & 3;
    const int mw   = w >> 1,    nw  = w & 1;
    const int grp  = nw * 4 + tig;
    const int z    = blockIdx.x;
    const int rowBase = blockIdx.y * 128;

    const float* Agl = p.A  + (long)z * p.aStride;
    const float* B1  = p.B1 + (long)z * p.b1Stride;

    float acc[2][8][4];
#pragma unroll
    for (int mt = 0; mt < 2; mt++)
#pragma unroll
        for (int nt = 0; nt < 8; nt++)
#pragma unroll
            for (int j = 0; j < 4; j++) acc[mt][nt][j] = 0.f;

    // ---------------- stage loads ----------------
    if (AGEN) {
#pragma unroll
        for (int c = 0; c < 4; c++) { loadB_chunk(Bs, B1, p.ldB1, p.ncols1, c, tid); cpcommit(); }
        // generate dh0 tile: relu(dx*W0[0,k] + dy*W0[1,k] + b0[k])
        if (tid < 128) {
            int nk = rowBase + tid;
            float dx = 0.f, dy = 0.f;
            if (nk < p.M) {
                long n = nk / KM;
                dx = p.ctrs[n * 2 + 0] - p.dReg[(long)nk * OUT2P + 58];
                dy = p.ctrs[n * 2 + 1] - p.dReg[(long)nk * OUT2P + 59];
            }
            red[tid] = dx; red[128 + tid] = dy;
        }
        __syncthreads();
        for (int i = tid; i < 128 * 128; i += 256) {
            int r = i >> 7, k = i & 127;
            float v = fmaf(red[r], __ldg(&p.dW0[k]),
                      fmaf(red[128 + r], __ldg(&p.dW0[DD + k]), __ldg(&p.db0[k])));
            As[r * LDA + k] = fmaxf(v, 0.f);
        }
    } else {
#pragma unroll
        for (int c = 0; c < 4; c++) {
            loadA_chunk(As, Agl, rowBase, p.M, c, tid);
            loadB_chunk(Bs, B1, p.ldB1, p.ncols1, c, tid);
            cpcommit();
        }
    }

    // ---------------- layer 1 (staged over 4 K-chunks) ----------------
#pragma unroll
    for (int c = 0; c < 4; c++) {
        switch (c) {
            case 0: cpwait<3>(); break;
            case 1: cpwait<TWOLAYER ? 3 : 2>(); break;
            case 2: cpwait<TWOLAYER ? 3 : 1>(); break;
            default: cpwait<TWOLAYER ? 3 : 0>(); break;
        }
        __syncthreads();
        compute_chunk(acc, As, Bs, c * 32, mw, nw, gid, tig);
        if (TWOLAYER) {               // recycle the dead Bs chunk for layer-2 weights
            __syncthreads();
            loadB_chunk(Bs, p.B2 + (long)z * p.b2Stride, DD, DD, c, tid);
            cpcommit();
        }
    }

    if (TWOLAYER) {
        // ---------------- mid epilogue: GN + relu -> Asv ----------------
        gn_stats(acc, red, red2, rstat, mw, gid, tig, grp, tid);
        const float* gg = p.g1  + (long)z * DD;
        const float* bb = p.bt1 + (long)z * DD;
#pragma unroll
        for (int mt = 0; mt < 2; mt++)
#pragma unroll
            for (int h = 0; h < 2; h++) {
                int r = mw * 32 + mt * 16 + gid + h * 8;
                float m = rstat[r], rs = rstat[128 + r];
#pragma unroll
                for (int nt = 0; nt < 8; nt++) {
                    int col = nw * 64 + nt * 8 + tig * 2;
                    float v0 = fmaxf((acc[mt][nt][h * 2]     - m) * rs * __ldg(gg + col)     + __ldg(bb + col),     0.f);
                    float v1 = fmaxf((acc[mt][nt][h * 2 + 1] - m) * rs * __ldg(gg + col + 1) + __ldg(bb + col + 1), 0.f);
                    *reinterpret_cast<float2*>(Asv + r * LDA + col) = make_float2(v0, v1);
                }
            }
#pragma unroll
        for (int mt = 0; mt < 2; mt++)
#pragma unroll
            for (int nt = 0; nt < 8; nt++)
#pragma unroll
                for (int j = 0; j < 4; j++) acc[mt][nt][j] = 0.f;

        // ---------------- layer 2 ----------------
#pragma unroll
        for (int c = 0; c < 4; c++) {
            switch (c) {
                case 0: cpwait<3>(); break;
                case 1: cpwait<2>(); break;
                case 2: cpwait<1>(); break;
                default: cpwait<0>(); break;
            }
            __syncthreads();
            compute_chunk(acc, Asv, Bs, c * 32, mw, nw, gid, tig);
        }
    }

    // ---------------- out epilogue ----------------
    if (EPIO == 0) {
#pragma unroll
        for (int mt = 0; mt < 2; mt++)
#pragma unroll
            for (int h = 0; h < 2; h++) {
                int r = mw * 32 + mt * 16 + gid + h * 8;
                int n = rowBase + r;
                if (n < p.M) {
#pragma unroll
                    for (int nt = 0; nt < 8; nt++) {
                        int col = nw * 64 + nt * 8 + tig * 2;
                        *reinterpret_cast<float2*>(p.Out + ((long)z * p.M + n) * DD + col) =
                            make_float2(acc[mt][nt][h * 2], acc[mt][nt][h * 2 + 1]);
                    }
                }
            }
        return;
    }
    if (EPIO == 4) {
#pragma unroll
        for (int mt = 0; mt < 2; mt++)
#pragma unroll
            for (int h = 0; h < 2; h++) {
                int r = mw * 32 + mt * 16 + gid + h * 8;
                int n = rowBase + r;
                if (n < p.M) {
                    float2 cc = *reinterpret_cast<const float2*>(p.ctrs + (long)n * 2);
#pragma unroll
                    for (int nt = 0; nt < 8; nt++) {
                        int col = nw * 64 + nt * 8 + tig * 2;
                        if (col < OUT2P) {
                            float v0 = acc[mt][nt][h * 2]     + __ldg(p.biasN + z * OUT2P + col)     + cc.x;
                            float v1 = acc[mt][nt][h * 2 + 1] + __ldg(p.biasN + z * OUT2P + col + 1) + cc.y;
                            *reinterpret_cast<float2*>(p.Out + ((long)n * KM + z) * OUT2P + col) =
                                make_float2(v0, v1);
                        }
                    }
                }
            }
        return;
    }

    // EPIO 2/3/5: GroupNorm paths
    if (EPIO == 3) {   // pre-GN add of a2[n/6]
#pragma unroll
        for (int mt = 0; mt < 2; mt++)
#pragma unroll
            for (int h = 0; h < 2; h++) {
                int r = mw * 32 + mt * 16 + gid + h * 8;
                int n = rowBase + r;
                if (n < p.M) {
                    const float* pa = p.pre + (long)(n / KM) * DD;
#pragma unroll
                    for (int nt = 0; nt < 8; nt++) {
                        int col = nw * 64 + nt * 8 + tig * 2;
                        float2 pv = *reinterpret_cast<const float2*>(pa + col);
                        acc[mt][nt][h * 2]     += pv.x;
                        acc[mt][nt][h * 2 + 1] += pv.y;
                    }
                }
            }
    }
    gn_stats(acc, red, red2, rstat, mw, gid, tig, grp, tid);
    {
        const float* gg = p.g2  + (long)z * DD;
        const float* bb = p.bt2 + (long)z * DD;
#pragma unroll
        for (int mt = 0; mt < 2; mt++)
#pragma unroll
            for (int h = 0; h < 2; h++) {
                int r = mw * 32 + mt * 16 + gid + h * 8;
                int n = rowBase + r;
                float m = rstat[r], rs = rstat[128 + r];
                float ds = 0.f;
#pragma unroll
                for (int nt = 0; nt < 8; nt++) {
                    int col = nw * 64 + nt * 8 + tig * 2;
                    float v0 = (acc[mt][nt][h * 2]     - m) * rs * __ldg(gg + col)     + __ldg(bb + col);
                    float v1 = (acc[mt][nt][h * 2 + 1] - m) * rs * __ldg(gg + col + 1) + __ldg(bb + col + 1);
                    if (EPIO == 2 || EPIO == 5) {   // residual = original layer-1 A tile (smem)
                        v0 += As[r * LDA + col];
                        v1 += As[r * LDA + col + 1];
                    }
                    v0 = fmaxf(v0, 0.f); v1 = fmaxf(v1, 0.f);
                    if (EPIO == 5) {
                        ds += v0 * __ldg(p.wo + col) + v1 * __ldg(p.wo + col + 1);
                    } else if (n < p.M) {
                        *reinterpret_cast<float2*>(p.Out + ((long)z * p.M + n) * DD + col) =
                            make_float2(v0, v1);
                    }
                }
                if (EPIO == 5) red[r * 9 + grp] = ds;
            }
    }
    if (EPIO == 5) {
        __syncthreads();
        if (tid < 128) {
            float s = 0.f;
#pragma unroll
            for (int g = 0; g < 8; g++) s += red[tid * 9 + g];
            int n = rowBase + tid;
            if (n < p.M) p.clsOut[n] = s + __ldg(p.wob);
        }
    }
}

// softmax over K=6, stable descending sort, reorder cls + reg into d_out
__global__ void final_k(const float* __restrict__ clsRaw, const float* __restrict__ reg,
                        float* __restrict__ out) {
    long gw = ((long)blockIdx.x * blockDim.x + threadIdx.x) >> 5;
    int lane = threadIdx.x & 31;
    if (gw >= NACT) return;
    long n = gw;
    float v[KM];
#pragma unroll
    for (int k = 0; k < KM; k++) v[k] = clsRaw[n * KM + k];
    float mx = v[0];
#pragma unroll
    for (int k = 1; k < KM; k++) mx = fmaxf(mx, v[k]);
    float e[KM]; float s = 0.f;
#pragma unroll
    for (int k = 0; k < KM; k++) { e[k] = expf(v[k] - mx); s += e[k]; }
    float inv = 1.f / s;
    int order[KM]; bool used[KM];
#pragma unroll
    for (int k = 0; k < KM; k++) used[k] = false;
#pragma unroll
    for (int j = 0; j < KM; j++) {
        int best = 0; float bv = -1e30f;
#pragma unroll
        for (int k = 0; k < KM; k++)
            if (!used[k] && v[k] > bv) { bv = v[k]; best = k; }
        used[best] = true;
        order[j] = best;
    }
    if (lane < KM) out[n * KM + lane] = e[order[lane]] * inv;
    const float* src0 = reg + n * KM * OUT2P;
    float* dst0 = out + OFF_REG + n * KM * OUT2P;
#pragma unroll
    for (int j = 0; j < KM; j++) {
        const float* src = src0 + order[j] * OUT2P;
        float* dst = dst0 + (long)j * OUT2P;
        for (int t = lane; t < OUT2P; t += 32) dst[t] = src[t];
    }
}

extern "C" void kernel_launch(void* const* d_in, const int* in_sizes, int n_in,
                              void* d_out, int out_size) {
    const float* actors  = (const float*)d_in[0];
    const float* ctrs    = (const float*)d_in[1];
    const float* pred_W1 = (const float*)d_in[2];
    const float* pred_g1 = (const float*)d_in[3];
    const float* pred_b1 = (const float*)d_in[4];
    const float* pred_W2 = (const float*)d_in[5];
    const float* pred_g2 = (const float*)d_in[6];
    const float* pred_b2 = (const float*)d_in[7];
    const float* pred_Wo = (const float*)d_in[8];
    const float* pred_bo = (const float*)d_in[9];
    const float* dist_W0 = (const float*)d_in[10];
    const float* dist_b0 = (const float*)d_in[11];
    const float* dist_W1 = (const float*)d_in[12];
    const float* dist_g1 = (const float*)d_in[13];
    const float* dist_b1 = (const float*)d_in[14];
    const float* agt_W   = (const float*)d_in[15];
    const float* agt_g   = (const float*)d_in[16];
    const float* agt_b   = (const float*)d_in[17];
    const float* cls_W1  = (const float*)d_in[18];
    const float* cls_g1  = (const float*)d_in[19];
    const float* cls_b1  = (const float*)d_in[20];
    const float* cls_W2  = (const float*)d_in[21];
    const float* cls_g2  = (const float*)d_in[22];
    const float* cls_b2  = (const float*)d_in[23];
    const float* cls_Wo  = (const float*)d_in[24];
    const float* cls_bo  = (const float*)d_in[25];
    float* out = (float*)d_out;

    float *buf2, *a2, *reg, *clsraw;
    cudaGetSymbolAddress((void**)&buf2,   g_buf2);
    cudaGetSymbolAddress((void**)&a2,     g_a2);
    cudaGetSymbolAddress((void**)&reg,    g_reg);
    cudaGetSymbolAddress((void**)&clsraw, g_cls);
    float* feats = out + OFF_FEATS;

    cudaFuncSetAttribute(fused_k<true,  false, 2>, cudaFuncAttributeMaxDynamicSharedMemorySize, SMEM_BYTES);
    cudaFuncSetAttribute(fused_k<false, false, 4>, cudaFuncAttributeMaxDynamicSharedMemorySize, SMEM_BYTES);
    cudaFuncSetAttribute(fused_k<false, false, 0>, cudaFuncAttributeMaxDynamicSharedMemorySize, SMEM_BYTES);
    cudaFuncSetAttribute(fused_k<true,  true,  3>, cudaFuncAttributeMaxDynamicSharedMemorySize, SMEM_BYTES);
    cudaFuncSetAttribute(fused_k<true,  false, 5>, cudaFuncAttributeMaxDynamicSharedMemorySize, SMEM_BYTES);

    const int gy_N  = (NACT + 127) / 128;          // 782
    const int gy_NK = ((int)TOT_NK + 127) / 128;   // 4688

    KParams p;

    // 1. pred12 (two-layer, resid = actors from smem)
    p = {}; p.A = actors; p.aStride = 0;
    p.B1 = pred_W1; p.b1Stride = (long)DD * DD; p.ldB1 = DD; p.ncols1 = DD;
    p.B2 = pred_W2; p.b2Stride = (long)DD * DD;
    p.M = NACT; p.g1 = pred_g1; p.bt1 = pred_b1; p.g2 = pred_g2; p.bt2 = pred_b2;
    p.Out = buf2;
    fused_k<true, false, 2><<<dim3(KM, gy_N), 256, SMEM_BYTES>>>(p);

    // 2. predo (single layer, bias + ctr, reg layout)
    p = {}; p.A = buf2; p.aStride = (long)NACT * DD;
    p.B1 = pred_Wo; p.b1Stride = (long)DD * OUT2P; p.ldB1 = OUT2P; p.ncols1 = OUT2P;
    p.M = NACT; p.Out = reg; p.biasN = pred_bo; p.ctrs = ctrs;
    fused_k<false, false, 4><<<dim3(KM, gy_N), 256, SMEM_BYTES>>>(p);

    // 3. a2 = actors @ agt_W[128:256]
    p = {}; p.A = actors; p.aStride = 0;
    p.B1 = agt_W + DD * DD; p.b1Stride = 0; p.ldB1 = DD; p.ncols1 = DD;
    p.M = NACT; p.Out = a2;
    fused_k<false, false, 0><<<dim3(1, gy_N), 256, SMEM_BYTES>>>(p);

    // 4. distagt (A generated; two-layer; pre-add a2; out -> feats)
    p = {}; p.A = nullptr; p.aStride = 0;
    p.B1 = dist_W1; p.b1Stride = 0; p.ldB1 = DD; p.ncols1 = DD;
    p.B2 = agt_W;  p.b2Stride = 0;
    p.M = (int)TOT_NK; p.g1 = dist_g1; p.bt1 = dist_b1; p.g2 = agt_g; p.bt2 = agt_b;
    p.Out = feats; p.pre = a2;
    p.ctrs = ctrs; p.dW0 = dist_W0; p.db0 = dist_b0; p.dReg = reg;
    fused_k<true, true, 3><<<dim3(1, gy_NK), 256, SMEM_BYTES>>>(p);

    // 5. cls12 (two-layer, resid = feats from smem, fused Wo dot)
    p = {}; p.A = feats; p.aStride = 0;
    p.B1 = cls_W1; p.b1Stride = 0; p.ldB1 = DD; p.ncols1 = DD;
    p.B2 = cls_W2; p.b2Stride = 0;
    p.M = (int)TOT_NK; p.g1 = cls_g1; p.bt1 = cls_b1; p.g2 = cls_g2; p.bt2 = cls_b2;
    p.wo = cls_Wo; p.wob = cls_bo; p.clsOut = clsraw;
    fused_k<true, false, 5><<<dim3(1, gy_NK), 256, SMEM_BYTES>>>(p);

    // 6. softmax + stable sort + gather
    {
        long threads = (long)NACT * 32;
        final_k<<<(int)((threads + 255) / 256), 256>>>(clsraw, reg, out);
    }
}